// round 2
// baseline (speedup 1.0000x reference)
#include <cuda_runtime.h>
#include <cuda_bf16.h>

// SpanRepLayer: start/inner/end maxpool span extraction.
// B=8, K=2048 spans, S=1024, H=256, W=24, WIN=3.
// One warp per span; lane owns 8 channels (2 x float4).

constexpr int Bc = 8;
constexpr int Kc = 2048;
constexpr int Sc = 1024;
constexpr int Hc = 256;
constexpr int WINc = 3;

__device__ __forceinline__ float4 f4max(float4 a, float4 b) {
    return make_float4(fmaxf(a.x, b.x), fmaxf(a.y, b.y),
                       fmaxf(a.z, b.z), fmaxf(a.w, b.w));
}

__global__ __launch_bounds__(256, 8)
void span_rep_kernel(const float* __restrict__ tok,
                     const int* __restrict__ ids,
                     const int* __restrict__ masks,   // bool widened to int32 by harness
                     float* __restrict__ out)
{
    const int span = blockIdx.x * 8 + (threadIdx.x >> 5);   // 8 warps/block
    const int lane = threadIdx.x & 31;

    float4* o4 = reinterpret_cast<float4*>(out + (size_t)span * (3 * Hc));

    if (masks[span] == 0) {
        const float4 z = make_float4(0.f, 0.f, 0.f, 0.f);
        #pragma unroll
        for (int i = 0; i < 6; i++) o4[lane + 32 * i] = z;
        return;
    }

    const int s = ids[2 * span];
    const int e = ids[2 * span + 1];
    const int scut = min(s + WINc, e);        // start region: [s, scut)
    const int ecut = max(e - WINc, s);        // end region:   [ecut, e)
    const bool has_inner = (e - s) > 2 * WINc;

    const int b = span >> 11;                 // K = 2048
    const float4* base = reinterpret_cast<const float4*>(tok + (size_t)b * Sc * Hc);

    const float NEG = __int_as_float(0xff800000); // -inf
    float4 sm0 = make_float4(NEG, NEG, NEG, NEG), sm1 = sm0;
    float4 em0 = sm0, em1 = sm0;
    float4 im0 = sm0, im1 = sm0;

    #pragma unroll 4
    for (int t = s; t < e; t++) {
        const float4* r = base + (size_t)t * (Hc / 4);
        const float4 a = __ldg(r + lane);
        const float4 c = __ldg(r + lane + 32);
        if (t < scut)       { sm0 = f4max(sm0, a); sm1 = f4max(sm1, c); }
        if (t >= ecut)      { em0 = f4max(em0, a); em1 = f4max(em1, c); }
        else if (t >= scut) { im0 = f4max(im0, a); im1 = f4max(im1, c); }
        // inner region [scut, ecut) is empty whenever width <= 2*WIN,
        // which matches the reference's (width > 2*WIN) gate exactly.
    }

    if (!has_inner) { im0 = sm0; im1 = sm1; }

    // layout per span: start[0:256) | inner[256:512) | end[512:768)
    o4[lane]            = sm0;  o4[lane + 32]  = sm1;
    o4[64 + lane]       = im0;  o4[96 + lane]  = im1;
    o4[128 + lane]      = em0;  o4[160 + lane] = em1;
}

extern "C" void kernel_launch(void* const* d_in, const int* in_sizes, int n_in,
                              void* d_out, int out_size)
{
    const float* tok   = (const float*)d_in[0];
    const int*   ids   = (const int*)d_in[1];
    const int*   masks = (const int*)d_in[2];
    float*       out   = (float*)d_out;

    const int total_spans = Bc * Kc;             // 16384
    span_rep_kernel<<<total_spans / 8, 256>>>(tok, ids, masks, out);
}

// round 3
// speedup vs baseline: 3.4176x; 3.4176x over previous
#include <cuda_runtime.h>
#include <cuda_bf16.h>

// SpanRepLayer via sparse-table (pow2 window-max pyramid) range-max.
// B=8, K=2048, S=1024, H=256, W=24, WIN=3.

constexpr int Bc = 8;
constexpr int Kc = 2048;
constexpr int Sc = 1024;
constexpr int Hc = 256;
constexpr int H4 = Hc / 4;      // 64 float4 per row
constexpr int WINc = 3;

// Pyramid levels: Mp[b][t][h] = max(tok[b][t..t+p)[h]) (clamped at seq end;
// clamped entries are never queried). 8 MB each.
__device__ float4 g_M2 [Bc * Sc * H4];
__device__ float4 g_M4 [Bc * Sc * H4];
__device__ float4 g_M8 [Bc * Sc * H4];
__device__ float4 g_M16[Bc * Sc * H4];

__device__ __forceinline__ float4 f4max(float4 a, float4 b) {
    return make_float4(fmaxf(a.x, b.x), fmaxf(a.y, b.y),
                       fmaxf(a.z, b.z), fmaxf(a.w, b.w));
}

// ---------------------------------------------------------------------------
// Pyramid build: each block produces 32 t-rows x 32 channels for all 4 levels.
// Needs 32+15=47 input rows in shared memory.
// ---------------------------------------------------------------------------
constexpr int TS  = 32;   // t-rows per block
constexpr int CH4 = 8;    // float4 per channel chunk (32 floats)

__global__ __launch_bounds__(256)
void build_pyramid(const float* __restrict__ tok)
{
    __shared__ float4 sm[TS + 15][CH4];

    const int tid = threadIdx.x;
    const int ch  = blockIdx.x % (H4 / CH4);               // 8 chunks
    const int ts  = (blockIdx.x / (H4 / CH4)) % (Sc / TS); // 32 tiles
    const int b   = blockIdx.x / ((H4 / CH4) * (Sc / TS)); // 8 batches
    const int t0  = ts * TS;

    const float4* src = reinterpret_cast<const float4*>(tok)
                      + (size_t)b * Sc * H4 + ch * CH4;

    for (int i = tid; i < (TS + 15) * CH4; i += 256) {
        const int r = i / CH4, c = i % CH4;
        const int t = min(t0 + r, Sc - 1);
        sm[r][c] = __ldg(src + (size_t)t * H4 + c);
    }
    __syncthreads();

    const int r = tid / CH4;     // 0..31
    const int c = tid % CH4;     // 0..7

    float4 v = sm[r][c];
    v = f4max(v, sm[r + 1][c]);                       const float4 m2 = v;
    v = f4max(v, sm[r + 2][c]);
    v = f4max(v, sm[r + 3][c]);                       const float4 m4 = v;
    #pragma unroll
    for (int k = 4; k < 8; k++)  v = f4max(v, sm[r + k][c]);
    const float4 m8 = v;
    #pragma unroll
    for (int k = 8; k < 16; k++) v = f4max(v, sm[r + k][c]);
    const float4 m16 = v;

    const size_t o = (size_t)b * Sc * H4 + (size_t)(t0 + r) * H4
                   + ch * CH4 + c;
    g_M2[o]  = m2;
    g_M4[o]  = m4;
    g_M8[o]  = m8;
    g_M16[o] = m16;
}

// ---------------------------------------------------------------------------
// Span kernel: one warp per span, 12 independent LDG.128 per lane.
// ---------------------------------------------------------------------------
__device__ __forceinline__ const float4* level_base(const float4* tok4, int w, int& p)
{
    if (w >= 16) { p = 16; return g_M16; }
    if (w >= 8)  { p = 8;  return g_M8;  }
    if (w >= 4)  { p = 4;  return g_M4;  }
    if (w >= 2)  { p = 2;  return g_M2;  }
    p = 1; return tok4;
}

__global__ __launch_bounds__(256, 8)
void span_rep_kernel(const float* __restrict__ tok,
                     const int* __restrict__ ids,
                     const int* __restrict__ masks,   // bool widened to int32
                     float* __restrict__ out)
{
    const int span = blockIdx.x * 8 + (threadIdx.x >> 5);
    const int lane = threadIdx.x & 31;

    float4* o4 = reinterpret_cast<float4*>(out + (size_t)span * (3 * Hc));

    if (masks[span] == 0) {
        const float4 z = make_float4(0.f, 0.f, 0.f, 0.f);
        #pragma unroll
        for (int i = 0; i < 6; i++) o4[lane + 32 * i] = z;
        return;
    }

    const int s = ids[2 * span];
    const int e = ids[2 * span + 1];
    const int w = e - s;

    const float4* tok4 = reinterpret_cast<const float4*>(tok);
    const size_t base = (size_t)(span >> 11) * Sc * H4;   // batch offset

    // start region [s, s+ws), ws in {1,2,3}
    const int ws = min(WINc, w);
    int ps; const float4* Ps = level_base(tok4, ws, ps);
    const float4* sa = Ps + base + (size_t)s * H4;
    const float4* sb = Ps + base + (size_t)(s + ws - ps) * H4;

    // end region [e-we, e), we in {1,2,3}
    const int we = min(WINc, w);
    int pe; const float4* Pe = level_base(tok4, we, pe);
    const float4* ea = Pe + base + (size_t)(e - we) * H4;
    const float4* eb = Pe + base + (size_t)(e - pe) * H4;

    // inner region [s+3, e-3), width w-6 in [1,18] when w > 6; else alias start
    const float4 *ia, *ib;
    if (w > 2 * WINc) {
        int pi; const float4* Pi = level_base(tok4, w - 2 * WINc, pi);
        ia = Pi + base + (size_t)(s + WINc) * H4;
        ib = Pi + base + (size_t)(e - WINc - pi) * H4;
    } else {
        ia = sa; ib = sb;   // inner := start (reference's all--inf fallback)
    }

    // 12 independent loads, one latency window.
    const float4 sa0 = __ldg(sa + lane), sa1 = __ldg(sa + lane + 32);
    const float4 sb0 = __ldg(sb + lane), sb1 = __ldg(sb + lane + 32);
    const float4 ea0 = __ldg(ea + lane), ea1 = __ldg(ea + lane + 32);
    const float4 eb0 = __ldg(eb + lane), eb1 = __ldg(eb + lane + 32);
    const float4 ia0 = __ldg(ia + lane), ia1 = __ldg(ia + lane + 32);
    const float4 ib0 = __ldg(ib + lane), ib1 = __ldg(ib + lane + 32);

    // layout per span: start[0:256) | inner[256:512) | end[512:768)
    o4[lane]       = f4max(sa0, sb0);  o4[lane + 32]  = f4max(sa1, sb1);
    o4[lane + 64]  = f4max(ia0, ib0);  o4[lane + 96]  = f4max(ia1, ib1);
    o4[lane + 128] = f4max(ea0, eb0);  o4[lane + 160] = f4max(ea1, eb1);
}

extern "C" void kernel_launch(void* const* d_in, const int* in_sizes, int n_in,
                              void* d_out, int out_size)
{
    const float* tok   = (const float*)d_in[0];
    const int*   ids   = (const int*)d_in[1];
    const int*   masks = (const int*)d_in[2];
    float*       out   = (float*)d_out;

    build_pyramid<<<Bc * (Sc / TS) * (H4 / CH4), 256>>>(tok);   // 2048 blocks
    span_rep_kernel<<<(Bc * Kc) / 8, 256>>>(tok, ids, masks, out);
}

// round 4
// speedup vs baseline: 3.6809x; 1.0770x over previous
#include <cuda_runtime.h>
#include <cuda_bf16.h>

// SpanRepLayer via window-max pyramid (levels 2,3,4,8) range-max.
// B=8, K=2048, S=1024, H=256, W=24, WIN=3.

constexpr int Bc = 8;
constexpr int Kc = 2048;
constexpr int Sc = 1024;
constexpr int Hc = 256;
constexpr int H4 = Hc / 4;      // 64 float4 per row
constexpr int WINc = 3;

// Mp[b][t][h] = max(tok[b][t..t+p)[h]); 8 MB each.
__device__ float4 g_M2[Bc * Sc * H4];
__device__ float4 g_M3[Bc * Sc * H4];
__device__ float4 g_M4[Bc * Sc * H4];
__device__ float4 g_M8[Bc * Sc * H4];

__device__ __forceinline__ float4 f4max(float4 a, float4 b) {
    return make_float4(fmaxf(a.x, b.x), fmaxf(a.y, b.y),
                       fmaxf(a.z, b.z), fmaxf(a.w, b.w));
}

// ---------------------------------------------------------------------------
// Pyramid build by log-doubling in shared memory.
// Tile: 128 t-rows x 32 channels (8 float4). Halo 7 rows.
// ---------------------------------------------------------------------------
constexpr int TS   = 128;
constexpr int RA   = TS + 7;    // 135 rows in buffer A
constexpr int RB   = TS + 6;    // 134 rows in buffer B (level-2)
constexpr int R4   = TS + 4;    // 132 rows of level-4 needed (M8 reads r+4)
constexpr int CH4  = 8;

__global__ __launch_bounds__(256)
void build_pyramid(const float* __restrict__ tok)
{
    __shared__ float4 A[RA][CH4];   // tok rows, later level-4
    __shared__ float4 B[RB][CH4];   // level-2

    const int tid = threadIdx.x;
    const int ch  = blockIdx.x & 7;               // 8 channel chunks
    const int ts  = (blockIdx.x >> 3) & 7;        // 8 t-tiles
    const int b   = blockIdx.x >> 6;              // 8 batches
    const int t0  = ts * TS;

    const float4* src = reinterpret_cast<const float4*>(tok)
                      + (size_t)b * Sc * H4 + ch * CH4;
    const size_t obase = (size_t)b * Sc * H4 + (size_t)t0 * H4 + ch * CH4;

    // fill A with tok rows [t0, t0+135), clamped (clamped rows never queried)
    #pragma unroll
    for (int j = 0; j < (RA * CH4 + 255) / 256; j++) {
        const int i = tid + j * 256;
        if (i < RA * CH4) {
            const int r = i / CH4, c = i % CH4;
            A[r][c] = __ldg(src + (size_t)min(t0 + r, Sc - 1) * H4 + c);
        }
    }
    __syncthreads();

    // level 2
    #pragma unroll
    for (int j = 0; j < (RB * CH4 + 255) / 256; j++) {
        const int i = tid + j * 256;
        if (i < RB * CH4) {
            const int r = i / CH4, c = i % CH4;
            const float4 v = f4max(A[r][c], A[r + 1][c]);
            B[r][c] = v;
            if (r < TS) g_M2[obase + (size_t)r * H4 + c] = v;
        }
    }
    __syncthreads();

    // level 3 (leaf: global only) + level 4 into registers
    float4 l4[(R4 * CH4 + 255) / 256];
    #pragma unroll
    for (int j = 0; j < (R4 * CH4 + 255) / 256; j++) {
        const int i = tid + j * 256;
        if (i < R4 * CH4) {
            const int r = i / CH4, c = i % CH4;
            if (r < TS) g_M3[obase + (size_t)r * H4 + c] = f4max(B[r][c], A[r + 2][c]);
            l4[j] = f4max(B[r][c], B[r + 2][c]);
        }
    }
    __syncthreads();

    // commit level 4 into A (overwrites tok rows) + global
    #pragma unroll
    for (int j = 0; j < (R4 * CH4 + 255) / 256; j++) {
        const int i = tid + j * 256;
        if (i < R4 * CH4) {
            const int r = i / CH4, c = i % CH4;
            A[r][c] = l4[j];
            if (r < TS) g_M4[obase + (size_t)r * H4 + c] = l4[j];
        }
    }
    __syncthreads();

    // level 8
    #pragma unroll
    for (int j = 0; j < (TS * CH4 + 255) / 256; j++) {
        const int i = tid + j * 256;
        if (i < TS * CH4) {
            const int r = i / CH4, c = i % CH4;
            g_M8[obase + (size_t)r * H4 + c] = f4max(A[r][c], A[r + 4][c]);
        }
    }
}

// ---------------------------------------------------------------------------
// Span kernel: one warp per span, 5 rows (10 LDG.128/lane), branchless batch.
// ---------------------------------------------------------------------------
__global__ __launch_bounds__(512)
void span_rep_kernel(const float* __restrict__ tok,
                     const int* __restrict__ ids,
                     const int* __restrict__ masks,   // bool widened to int32
                     float* __restrict__ out)
{
    const int span = blockIdx.x * 16 + (threadIdx.x >> 5);
    const int lane = threadIdx.x & 31;

    float4* o4 = reinterpret_cast<float4*>(out + (size_t)span * (3 * Hc));

    if (masks[span] == 0) {
        const float4 z = make_float4(0.f, 0.f, 0.f, 0.f);
        #pragma unroll
        for (int i = 0; i < 6; i++) o4[lane + 32 * i] = z;
        return;
    }

    const int2 se = __ldg(reinterpret_cast<const int2*>(ids) + span);
    const int s = se.x, e = se.y, w = e - s;

    const float4* tok4 = reinterpret_cast<const float4*>(tok)
                       + (size_t)(span >> 11) * Sc * H4;     // batch base
    const size_t boff = (size_t)(span >> 11) * Sc * H4;

    // start/end share window width lw = min(3,w): single row each.
    const int lw = min(w, WINc);
    const float4* Lse = (lw == 1) ? tok4
                      : (lw == 2) ? (g_M2 + boff) : (g_M3 + boff);
    const float4* rs = Lse + (size_t)s * H4;
    const float4* re = Lse + (size_t)(e - lw) * H4;

    // inner: width wp = w-6 in [1,18] when w>6; else alias start.
    const float4 *i0, *i1, *i2;
    if (w > 2 * WINc) {
        const int wp = w - 2 * WINc;
        const int a  = s + WINc;
        const float4* Li; int p;
        if (wp >= 8)      { Li = g_M8 + boff; p = 8; }
        else if (wp >= 4) { Li = g_M4 + boff; p = 4; }
        else if (wp == 3) { Li = g_M3 + boff; p = 3; }
        else if (wp == 2) { Li = g_M2 + boff; p = 2; }
        else              { Li = tok4;        p = 1; }
        i0 = Li + (size_t)a * H4;
        i1 = Li + (size_t)(a + wp - p) * H4;
        // 3rd window only needed for wp in {17,18}; else alias i1 (L1 hit).
        i2 = (wp > 2 * 8) ? Li + (size_t)(a + (wp >> 1) - 4) * H4 : i1;
    } else {
        i0 = rs; i1 = rs; i2 = rs;   // inner := start (all--inf fallback)
    }

    // 10 independent loads, one latency window.
    const float4 s0 = __ldg(rs + lane), s1 = __ldg(rs + lane + 32);
    const float4 e0 = __ldg(re + lane), e1 = __ldg(re + lane + 32);
    const float4 a0 = __ldg(i0 + lane), a1 = __ldg(i0 + lane + 32);
    const float4 b0 = __ldg(i1 + lane), b1 = __ldg(i1 + lane + 32);
    const float4 c0 = __ldg(i2 + lane), c1 = __ldg(i2 + lane + 32);

    // layout per span: start[0:256) | inner[256:512) | end[512:768)
    o4[lane]       = s0;                      o4[lane + 32]  = s1;
    o4[lane + 64]  = f4max(f4max(a0, b0), c0);
    o4[lane + 96]  = f4max(f4max(a1, b1), c1);
    o4[lane + 128] = e0;                      o4[lane + 160] = e1;
}

extern "C" void kernel_launch(void* const* d_in, const int* in_sizes, int n_in,
                              void* d_out, int out_size)
{
    const float* tok   = (const float*)d_in[0];
    const int*   ids   = (const int*)d_in[1];
    const int*   masks = (const int*)d_in[2];
    float*       out   = (float*)d_out;

    build_pyramid<<<Bc * (Sc / TS) * (H4 / CH4), 256>>>(tok);   // 512 blocks
    span_rep_kernel<<<(Bc * Kc) / 16, 512>>>(tok, ids, masks, out);
}

// round 5
// speedup vs baseline: 4.4600x; 1.2117x over previous
#include <cuda_runtime.h>

// SpanRepLayer, fully fused: per-block smem token slab + smem M3/M8 pyramids.
// B=8, K=2048, S=1024, H=256, W=24, WIN=3.

constexpr int Bc = 8;
constexpr int Kc = 2048;
constexpr int Sc = 1024;
constexpr int WINc = 3;

constexpr int TT = 32;          // span-start tile (rows of starts per block)
constexpr int NT = Sc / TT;     // 32 tiles
constexpr int R0 = 56;          // token rows resident   (max e-1 = t0+54)
constexpr int R3 = 53;          // M3 rows                (max idx e-3 <= t0+52)
constexpr int R8 = 45;          // M8 rows                (max idx e-11 <= t0+44)
constexpr int C4 = 32;          // float4 per row (128-channel half)
constexpr int LISTCAP = 192;    // avg 64 spans/tile, 192 = +16 sigma

__device__ __forceinline__ float4 f4max(float4 a, float4 b) {
    return make_float4(fmaxf(a.x, b.x), fmaxf(a.y, b.y),
                       fmaxf(a.z, b.z), fmaxf(a.w, b.w));
}

__global__ __launch_bounds__(512, 2)
void span_fused(const float* __restrict__ tok,
                const int* __restrict__ ids,
                const int* __restrict__ masks,   // bool widened to int32
                float* __restrict__ out)
{
    extern __shared__ float4 sm[];
    float4* T0 = sm;                       // R0*C4
    float4* M3 = sm + R0 * C4;             // R3*C4
    float4* M8 = sm + (R0 + R3) * C4;      // R8*C4
    __shared__ int list[LISTCAP];
    __shared__ int nspan;

    const int tid  = threadIdx.x;
    const int half = blockIdx.x & 1;             // channel half
    const int tile = (blockIdx.x >> 1) & (NT - 1);
    const int b    = blockIdx.x >> 6;
    const int t0   = tile * TT;

    if (tid == 0) nspan = 0;
    __syncthreads();

    // ---- load token slab (rows [t0, t0+56), 128 channels) ----
    const float4* g = reinterpret_cast<const float4*>(tok)
                    + (size_t)b * Sc * 64 + half * C4;
    #pragma unroll
    for (int j = 0; j < (R0 * C4 + 511) / 512; j++) {
        const int i = tid + j * 512;
        if (i < R0 * C4) {
            const int r = i >> 5, c = i & 31;
            T0[i] = __ldg(g + (size_t)min(t0 + r, Sc - 1) * 64 + c);
        }
    }

    // ---- scan this batch's spans, compact ones starting in our tile ----
    #pragma unroll
    for (int j = 0; j < Kc / 512; j++) {
        const int k = tid + j * 512;
        const int2 se = __ldg(reinterpret_cast<const int2*>(ids) + b * Kc + k);
        if ((se.x >> 5) == tile) {
            const int p = atomicAdd(&nspan, 1);
            if (p < LISTCAP) list[p] = k;
        }
    }
    __syncthreads();

    // ---- build M3[r] = max(T0[r..r+2]) ----
    #pragma unroll
    for (int j = 0; j < (R3 * C4 + 511) / 512; j++) {
        const int i = tid + j * 512;
        if (i < R3 * C4)
            M3[i] = f4max(f4max(T0[i], T0[i + C4]), T0[i + 2 * C4]);
    }
    __syncthreads();

    // ---- build M8[r] = max(M3[r], M3[r+3], T0[r+6], T0[r+7]) ----
    #pragma unroll
    for (int j = 0; j < (R8 * C4 + 511) / 512; j++) {
        const int i = tid + j * 512;
        if (i < R8 * C4)
            M8[i] = f4max(f4max(M3[i], M3[i + 3 * C4]),
                          f4max(T0[i + 6 * C4], T0[i + 7 * C4]));
    }
    __syncthreads();

    // ---- per-warp span processing ----
    const int wid = tid >> 5, lane = tid & 31;
    const int n = min(nspan, LISTCAP);

    for (int i = wid; i < n; i += 16) {
        const int k = list[i];
        const int span = b * Kc + k;
        // out layout per span: 192 float4 = start[0:64) inner[64:128) end[128:192)
        float4* o = reinterpret_cast<float4*>(out)
                  + (size_t)span * 192 + half * C4 + lane;

        if (__ldg(masks + span) == 0) {
            const float4 z = make_float4(0.f, 0.f, 0.f, 0.f);
            o[0] = z; o[64] = z; o[128] = z;
            continue;
        }

        const int2 se = __ldg(reinterpret_cast<const int2*>(ids) + span);
        const int ls = se.x - t0;          // [0,32)
        const int le = se.y - t0;          // <= 55
        const int w  = le - ls;

        float4 S, E;
        if (w >= 3)      { S = M3[ls * C4 + lane]; E = M3[(le - 3) * C4 + lane]; }
        else if (w == 2) { S = f4max(T0[ls * C4 + lane], T0[(ls + 1) * C4 + lane]); E = S; }
        else             { S = T0[ls * C4 + lane]; E = S; }

        const int wp = w - 2 * WINc;       // inner width
        const int a  = ls + WINc;
        float4 I;
        if (wp <= 0)      I = S;                                   // all--inf fallback
        else if (wp == 1) I = T0[a * C4 + lane];
        else if (wp == 2) I = f4max(T0[a * C4 + lane], T0[(a + 1) * C4 + lane]);
        else if (wp == 3) I = M3[a * C4 + lane];
        else if (wp <= 6) I = f4max(M3[a * C4 + lane], M3[(le - 6) * C4 + lane]);
        else if (wp == 7) I = f4max(f4max(M3[a * C4 + lane], M3[(a + 2) * C4 + lane]),
                                    M3[(a + 4) * C4 + lane]);
        else if (wp == 8) I = M8[a * C4 + lane];
        else if (wp <= 16) I = f4max(M8[a * C4 + lane], M8[(le - 11) * C4 + lane]);
        else               I = f4max(f4max(M8[a * C4 + lane],
                                           M8[(a + (wp >> 1) - 4) * C4 + lane]),
                                     M8[(le - 11) * C4 + lane]);

        o[0] = S; o[64] = I; o[128] = E;
    }
}

extern "C" void kernel_launch(void* const* d_in, const int* in_sizes, int n_in,
                              void* d_out, int out_size)
{
    const float* tok   = (const float*)d_in[0];
    const int*   ids   = (const int*)d_in[1];
    const int*   masks = (const int*)d_in[2];
    float*       out   = (float*)d_out;

    constexpr int SMEM = (R0 + R3 + R8) * C4 * (int)sizeof(float4);  // 78848 B
    static_assert(SMEM < 100 * 1024, "smem budget");
    cudaFuncSetAttribute(span_fused, cudaFuncAttributeMaxDynamicSharedMemorySize, SMEM);

    span_fused<<<Bc * NT * 2, 512, SMEM>>>(tok, ids, masks, out);   // 512 blocks
}

// round 6
// speedup vs baseline: 5.0491x; 1.1321x over previous
#include <cuda_runtime.h>

// SpanRepLayer, fused: smem token slab + smem M3 pyramid, global-free span phase.
// B=8, K=2048, S=1024, H=256, W=24, WIN=3.

constexpr int Bc = 8;
constexpr int Kc = 2048;
constexpr int Sc = 1024;
constexpr int WINc = 3;

constexpr int TT = 32;          // span-start tile
constexpr int NT = Sc / TT;     // 32 tiles
constexpr int R0 = 56;          // token rows resident (max queried row t0+54)
constexpr int R3 = 53;          // M3 rows (max queried idx t0+52)
constexpr int C4 = 32;          // float4 per row (128-channel half)
constexpr int LISTCAP = 192;    // mean 64 spans/tile, sigma ~8

__device__ __forceinline__ float4 f4max(float4 a, float4 b) {
    return make_float4(fmaxf(a.x, b.x), fmaxf(a.y, b.y),
                       fmaxf(a.z, b.z), fmaxf(a.w, b.w));
}

__global__ __launch_bounds__(512, 3)
void span_fused(const float* __restrict__ tok,
                const int* __restrict__ ids,
                const int* __restrict__ masks,   // bool widened to int32
                float* __restrict__ out)
{
    extern __shared__ float4 sm[];
    float4* T0 = sm;                       // R0*C4
    float4* M3 = sm + R0 * C4;             // R3*C4
    __shared__ int4 list[LISTCAP];         // (k, s, e, mask)
    __shared__ int nspan;

    const int tid  = threadIdx.x;
    const int half = blockIdx.x & 1;             // channel half
    const int tile = (blockIdx.x >> 1) & (NT - 1);
    const int b    = blockIdx.x >> 6;
    const int t0   = tile * TT;

    if (tid == 0) nspan = 0;
    __syncthreads();

    // ---- load token slab (rows [t0, t0+56), this block's 128 channels) ----
    const float4* g = reinterpret_cast<const float4*>(tok)
                    + (size_t)b * Sc * 64 + half * C4;
    #pragma unroll
    for (int j = 0; j < (R0 * C4 + 511) / 512; j++) {
        const int i = tid + j * 512;
        if (i < R0 * C4) {
            const int r = i >> 5, c = i & 31;
            T0[i] = __ldg(g + (size_t)min(t0 + r, Sc - 1) * 64 + c);
        }
    }

    // ---- scan batch spans; compact (k,s,e,mask) for starts in our tile ----
    #pragma unroll
    for (int j = 0; j < Kc / 512; j++) {
        const int k = tid + j * 512;
        const int2 se = __ldg(reinterpret_cast<const int2*>(ids) + b * Kc + k);
        if ((se.x >> 5) == tile) {
            const int m = __ldg(masks + b * Kc + k);
            const int p = atomicAdd(&nspan, 1);
            if (p < LISTCAP) list[p] = make_int4(k, se.x, se.y, m);
        }
    }
    __syncthreads();

    // ---- build M3[r] = max(T0[r..r+2]) ----
    #pragma unroll
    for (int j = 0; j < (R3 * C4 + 511) / 512; j++) {
        const int i = tid + j * 512;
        if (i < R3 * C4)
            M3[i] = f4max(f4max(T0[i], T0[i + C4]), T0[i + 2 * C4]);
    }
    __syncthreads();

    // ---- per-warp span processing: pure smem + STG ----
    const int wid = tid >> 5, lane = tid & 31;
    const int n = min(nspan, LISTCAP);

    for (int i = wid; i < n; i += 16) {
        const int4 sp = list[i];
        float4* o = reinterpret_cast<float4*>(out)
                  + (size_t)(b * Kc + sp.x) * 192 + half * C4 + lane;

        if (sp.w == 0) {
            const float4 z = make_float4(0.f, 0.f, 0.f, 0.f);
            o[0] = z; o[64] = z; o[128] = z;
            continue;
        }

        const int ls = sp.y - t0;          // [0,32)
        const int le = sp.z - t0;          // <= 55
        const int w  = le - ls;

        float4 S, E;
        if (w >= 3)      { S = M3[ls * C4 + lane]; E = M3[(le - 3) * C4 + lane]; }
        else if (w == 2) { S = f4max(T0[ls * C4 + lane], T0[(ls + 1) * C4 + lane]); E = S; }
        else             { S = T0[ls * C4 + lane]; E = S; }

        const int wp = w - 2 * WINc;       // inner width (<=18)
        const int a  = ls + WINc;
        float4 I;
        if (wp <= 0)      I = S;                                   // all--inf fallback
        else if (wp == 1) I = T0[a * C4 + lane];
        else if (wp == 2) I = f4max(T0[a * C4 + lane], T0[(a + 1) * C4 + lane]);
        else {
            I = M3[(a + wp - 3) * C4 + lane];
            for (int p = a; p < a + wp - 3; p += 3)                // <=5 iters
                I = f4max(I, M3[p * C4 + lane]);
        }

        o[0] = S; o[64] = I; o[128] = E;
    }
}

extern "C" void kernel_launch(void* const* d_in, const int* in_sizes, int n_in,
                              void* d_out, int out_size)
{
    const float* tok   = (const float*)d_in[0];
    const int*   ids   = (const int*)d_in[1];
    const int*   masks = (const int*)d_in[2];
    float*       out   = (float*)d_out;

    constexpr int SMEM = (R0 + R3) * C4 * (int)sizeof(float4);   // 55808 B
    cudaFuncSetAttribute(span_fused, cudaFuncAttributeMaxDynamicSharedMemorySize, SMEM);

    span_fused<<<Bc * NT * 2, 512, SMEM>>>(tok, ids, masks, out);  // 512 blocks
}